// round 6
// baseline (speedup 1.0000x reference)
#include <cuda_runtime.h>
#include <math.h>

#define NNODES 50000
#define NEDGES 1600000
#define ETOT   (NEDGES + NNODES)
#define INCH   64
#define HEADS  8
#define HID    16
#define HH     (HEADS*HID)   /* 128 */
#define NGRAPH 256
#define OUTC   32
#define CAP    128
#define GG     ((NNODES + 31) / 32)        /* gemm1 blocks = 1563 */
#define GH     ((ETOT + 255) / 256)        /* fill blocks  = 6446 */

// ---------------- scratch ----------------
__device__ __align__(16) float g_xl1[NNODES*HH];
__device__ __align__(16) float g_xr1[NNODES*HH];
__device__ __align__(16) float g_xl2[NNODES*HID];
__device__ __align__(16) float g_xr2[NNODES*HID];
__device__ __align__(16) float g_pool[NGRAPH*HID];
__device__ __align__(16) float g_cnt[NGRAPH];
__device__ int g_count[NNODES];
__device__ int g_slot[(size_t)NNODES * CAP];

__device__ __forceinline__ float elu1f(float v) { return v > 0.f ? v : expm1f(v); }
__device__ __forceinline__ float lrelu(float v) { return fmaxf(v, 0.2f * v); }

// ---------------- zero: count + pool + cnt ----------------
__global__ void zero_kernel() {
    int i = blockIdx.x * blockDim.x + threadIdx.x;
    if (i < NNODES) g_count[i] = 0;
    if (i < NGRAPH * HID) g_pool[i] = 0.f;
    if (i < NGRAPH) g_cnt[i] = 0.f;
}

// ---------------- fused: gemm1 (first GG blocks) || bucket-fill (rest) ----------------
__global__ void __launch_bounds__(256) fusedA_kernel(
        const float* __restrict__ x,
        const float* __restrict__ wl, const float* __restrict__ bl,
        const float* __restrict__ wr, const float* __restrict__ br,
        const int* __restrict__ src, const int* __restrict__ dst) {
    if (blockIdx.x >= GG) {
        int e = (blockIdx.x - GG) * 256 + threadIdx.x;
        if (e < ETOT) {
            int s, d;
            if (e < NEDGES) { s = src[e]; d = dst[e]; } else { s = e - NEDGES; d = s; }
            int pos = atomicAdd(&g_count[d], 1);
            if (pos < CAP) g_slot[(size_t)d * CAP + pos] = s;
        }
        return;
    }
    __shared__ __align__(16) float xs[8][INCH];
    int tid = threadIdx.x;
    int c = tid & (HH - 1);
    const float* w = (tid < HH) ? wl : wr;
    float bias = (tid < HH) ? bl[c] : br[c];
    float wreg[INCH];
    #pragma unroll
    for (int k = 0; k < INCH; k++) wreg[k] = __ldg(&w[k * HH + c]);
    float* outp = (tid < HH) ? g_xl1 : g_xr1;
    int node0 = blockIdx.x * 32;
    for (int base = 0; base < 32; base += 8) {
        int n0 = node0 + base;
        __syncthreads();
        if (tid < 128) {
            int nn = tid >> 4, k4 = tid & 15;
            int g = n0 + nn;
            float4 v = (g < NNODES) ? ((const float4*)(x + (size_t)g * INCH))[k4]
                                    : make_float4(0.f, 0.f, 0.f, 0.f);
            ((float4*)&xs[nn][0])[k4] = v;
        }
        __syncthreads();
        float acc[8];
        #pragma unroll
        for (int j = 0; j < 8; j++) acc[j] = bias;
        #pragma unroll
        for (int k4 = 0; k4 < 16; k4++) {
            #pragma unroll
            for (int j = 0; j < 8; j++) {
                float4 xv = ((const float4*)&xs[j][0])[k4];
                acc[j] = fmaf(xv.x, wreg[4 * k4 + 0],
                         fmaf(xv.y, wreg[4 * k4 + 1],
                         fmaf(xv.z, wreg[4 * k4 + 2],
                         fmaf(xv.w, wreg[4 * k4 + 3], acc[j]))));
            }
        }
        #pragma unroll
        for (int j = 0; j < 8; j++) {
            int g = n0 + j;
            if (g < NNODES) outp[(size_t)g * HH + c] = acc[j];
        }
    }
}

// ---------------- conv1 edge pass FUSED WITH conv2 node transform ----------------
// One warp per dst node (grid = exactly 50000 warps).
// Phase 1: softmax-aggregate over incoming edges (registers only).
// Phase 2: o = elu(agg/den + bias1) -> immediately compute [xl2|xr2] = o @ [wl2|wr2]
//          via per-lane partials + recursive-halving warp transpose-reduce.
__device__ __forceinline__ float edge1_exp(float4 xv, float4 xr, float4 aw) {
    float p = lrelu(xv.x + xr.x) * aw.x + lrelu(xv.y + xr.y) * aw.y
            + lrelu(xv.z + xr.z) * aw.z + lrelu(xv.w + xr.w) * aw.w;
    p += __shfl_xor_sync(0xffffffffu, p, 1);
    p += __shfl_xor_sync(0xffffffffu, p, 2);
    return __expf(p);
}

__global__ void __launch_bounds__(256, 3) edge1_fused_kernel(
        const float* __restrict__ att, const float* __restrict__ bias,
        const float* __restrict__ wl2, const float* __restrict__ bl2,
        const float* __restrict__ wr2, const float* __restrict__ br2) {
    __shared__ __align__(16) float wt[32][HH];   // transposed [wl2|wr2], 16KB
    __shared__ float b2s[32];
    int tid = threadIdx.x;
    // preload conv2 weights (transposed: wt[j][ch])
    #pragma unroll
    for (int u = 0; u < 16; u++) {
        int idx = tid * 16 + u;                  // 4096 entries
        int j = idx >> 7, ch = idx & 127;
        wt[j][ch] = (j < HID) ? __ldg(&wl2[ch * HID + j]) : __ldg(&wr2[ch * HID + (j - HID)]);
    }
    if (tid < 32) b2s[tid] = (tid < HID) ? bl2[tid] : br2[tid - HID];
    __syncthreads();

    int warp = (blockIdx.x * 256 + tid) >> 5;    // 0..49999 exactly
    int lane = tid & 31;
    int d = warp;
    float4 xr = ((const float4*)(g_xr1 + (size_t)d * HH))[lane];
    float4 aw = __ldg(&((const float4*)att)[lane]);
    float4 acc = make_float4(0.f, 0.f, 0.f, 0.f);
    float den = 0.f;
    int deg = min(g_count[d], CAP);
    const int* slot = g_slot + (size_t)d * CAP;
    for (int blk = 0; blk < deg; blk += 32) {
        int nn = min(32, deg - blk);             // warp-uniform
        int myidx = (lane < nn) ? slot[blk + lane] : 0;
        int j = 0;
        for (; j + 3 < nn; j += 4) {
            int s0 = __shfl_sync(0xffffffffu, myidx, j);
            int s1 = __shfl_sync(0xffffffffu, myidx, j + 1);
            int s2 = __shfl_sync(0xffffffffu, myidx, j + 2);
            int s3 = __shfl_sync(0xffffffffu, myidx, j + 3);
            float4 x0 = ((const float4*)(g_xl1 + (size_t)s0 * HH))[lane];
            float4 x1 = ((const float4*)(g_xl1 + (size_t)s1 * HH))[lane];
            float4 x2 = ((const float4*)(g_xl1 + (size_t)s2 * HH))[lane];
            float4 x3 = ((const float4*)(g_xl1 + (size_t)s3 * HH))[lane];
            float e0 = edge1_exp(x0, xr, aw);
            float e1 = edge1_exp(x1, xr, aw);
            float e2 = edge1_exp(x2, xr, aw);
            float e3 = edge1_exp(x3, xr, aw);
            acc.x += e0 * x0.x + e1 * x1.x + e2 * x2.x + e3 * x3.x;
            acc.y += e0 * x0.y + e1 * x1.y + e2 * x2.y + e3 * x3.y;
            acc.z += e0 * x0.z + e1 * x1.z + e2 * x2.z + e3 * x3.z;
            acc.w += e0 * x0.w + e1 * x1.w + e2 * x2.w + e3 * x3.w;
            den += (e0 + e1) + (e2 + e3);
        }
        for (; j < nn; j++) {
            int s0 = __shfl_sync(0xffffffffu, myidx, j);
            float4 x0 = ((const float4*)(g_xl1 + (size_t)s0 * HH))[lane];
            float e0 = edge1_exp(x0, xr, aw);
            acc.x += e0 * x0.x; acc.y += e0 * x0.y; acc.z += e0 * x0.z; acc.w += e0 * x0.w;
            den += e0;
        }
    }
    float inv = 1.f / (den + 1e-16f);
    float4 b = __ldg(&((const float4*)bias)[lane]);
    float4 o;
    o.x = elu1f(fmaf(acc.x, inv, b.x));
    o.y = elu1f(fmaf(acc.y, inv, b.y));
    o.z = elu1f(fmaf(acc.z, inv, b.z));
    o.w = elu1f(fmaf(acc.w, inv, b.w));

    // ---- conv2 transform: lane l holds channels [4l, 4l+4) of o ----
    float r[32];
    #pragma unroll
    for (int j = 0; j < 32; j++) {
        float4 wv = ((const float4*)&wt[j][0])[lane];
        r[j] = fmaf(o.x, wv.x, fmaf(o.y, wv.y, fmaf(o.z, wv.z, o.w * wv.w)));
    }
    // recursive-halving transpose-reduce: ends with lane j holding column j
    #pragma unroll
    for (int off = 16; off >= 1; off >>= 1) {
        bool upper = (lane & off) != 0;
        #pragma unroll
        for (int i = 0; i < off; i++) {
            float send = upper ? r[i] : r[i + off];
            float other = __shfl_xor_sync(0xffffffffu, send, off);
            r[i] = (upper ? r[i + off] : r[i]) + other;
        }
    }
    float res = r[0] + b2s[lane];
    if (lane < HID) g_xl2[(size_t)d * HID + lane] = res;
    else            g_xr2[(size_t)d * HID + (lane - HID)] = res;
}

// ---------------- conv2 fused edge pass + bias2 + ELU + mean-pool ----------------
__global__ void __launch_bounds__(256) edge2_fused_kernel(const float* __restrict__ att,
                                                          const float* __restrict__ bias,
                                                          const int* __restrict__ batch) {
    int warp = (blockIdx.x * blockDim.x + threadIdx.x) >> 5;
    if (warp >= NNODES) return;
    int lane = threadIdx.x & 31;
    int c = lane & 15;
    int sub = lane >> 4;
    int d = warp;
    float xr = g_xr2[(size_t)d * HID + c];
    float aw = __ldg(&att[c]);
    float acc = 0.f, den = 0.f;
    int deg = min(g_count[d], CAP);
    const int* slot = g_slot + (size_t)d * CAP;
    for (int blk = 0; blk < deg; blk += 32) {
        int nn = min(32, deg - blk);
        int myidx = (lane < nn) ? slot[blk + lane] : 0;
        int j = 0;
        for (; j + 3 < nn; j += 4) {
            int s0 = __shfl_sync(0xffffffffu, myidx, j + sub);
            int s1 = __shfl_sync(0xffffffffu, myidx, j + 2 + sub);
            float xl0 = g_xl2[(size_t)s0 * HID + c];
            float xl1 = g_xl2[(size_t)s1 * HID + c];
            float p0 = lrelu(xl0 + xr) * aw;
            float p1 = lrelu(xl1 + xr) * aw;
            p0 += __shfl_xor_sync(0xffffffffu, p0, 1);
            p1 += __shfl_xor_sync(0xffffffffu, p1, 1);
            p0 += __shfl_xor_sync(0xffffffffu, p0, 2);
            p1 += __shfl_xor_sync(0xffffffffu, p1, 2);
            p0 += __shfl_xor_sync(0xffffffffu, p0, 4);
            p1 += __shfl_xor_sync(0xffffffffu, p1, 4);
            p0 += __shfl_xor_sync(0xffffffffu, p0, 8);
            p1 += __shfl_xor_sync(0xffffffffu, p1, 8);
            float e0 = __expf(p0), e1 = __expf(p1);
            acc += e0 * xl0 + e1 * xl1;
            den += e0 + e1;
        }
        for (; j < nn; j += 2) {
            int take1 = (j + 1 < nn);
            int idx = j + (take1 ? sub : 0);
            int s = __shfl_sync(0xffffffffu, myidx, idx);
            float xl = g_xl2[(size_t)s * HID + c];
            float p = lrelu(xl + xr) * aw;
            p += __shfl_xor_sync(0xffffffffu, p, 1);
            p += __shfl_xor_sync(0xffffffffu, p, 2);
            p += __shfl_xor_sync(0xffffffffu, p, 4);
            p += __shfl_xor_sync(0xffffffffu, p, 8);
            bool ok = take1 || (sub == 0);
            float ex = ok ? __expf(p) : 0.f;
            acc += ex * xl;
            den += ex;
        }
    }
    acc += __shfl_xor_sync(0xffffffffu, acc, 16);
    den += __shfl_xor_sync(0xffffffffu, den, 16);
    if (sub == 0) {
        float o = elu1f(acc / (den + 1e-16f) + __ldg(&bias[c]));
        int b = batch[d];
        atomicAdd(&g_pool[b * HID + c], o);
        if (c == 0) atomicAdd(&g_cnt[b], 1.f);
    }
}

// ---------------- final MLP ----------------
__global__ void mlp_kernel(const float* __restrict__ w1, const float* __restrict__ b1,
                           const float* __restrict__ w2, const float* __restrict__ b2,
                           const float* __restrict__ w3, const float* __restrict__ b3,
                           float* __restrict__ out) {
    __shared__ float s1[HID * 32], sb1[32];
    __shared__ float s2[32 * HID], sb2[HID];
    __shared__ float s3[HID * 32], sb3[32];
    int tid = threadIdx.x;
    for (int i = tid; i < HID * 32; i += 256) s1[i] = w1[i];
    for (int i = tid; i < 32 * HID; i += 256) s2[i] = w2[i];
    for (int i = tid; i < HID * 32; i += 256) s3[i] = w3[i];
    if (tid < 32) { sb1[tid] = b1[tid]; sb3[tid] = b3[tid]; }
    if (tid < HID) sb2[tid] = b2[tid];
    __syncthreads();
    int b = tid;
    float cnt = fmaxf(g_cnt[b], 1.f);
    float h[HID];
    #pragma unroll
    for (int c = 0; c < HID; c++) h[c] = g_pool[b * HID + c] / cnt;
    float t1[32];
    #pragma unroll
    for (int j = 0; j < 32; j++) {
        float s = sb1[j];
        #pragma unroll
        for (int k = 0; k < HID; k++) s += h[k] * s1[k * 32 + j];
        t1[j] = elu1f(s);
    }
    float t2[HID];
    #pragma unroll
    for (int j = 0; j < HID; j++) {
        float s = sb2[j];
        #pragma unroll
        for (int k = 0; k < 32; k++) s += t1[k] * s2[k * HID + j];
        t2[j] = elu1f(s);
    }
    #pragma unroll
    for (int j = 0; j < 32; j++) {
        float s = sb3[j];
        #pragma unroll
        for (int k = 0; k < HID; k++) s += t2[k] * s3[k * 32 + j];
        out[b * 32 + j] = s;
    }
}

// ---------------- launch ----------------
extern "C" void kernel_launch(void* const* d_in, const int* in_sizes, int n_in,
                              void* d_out, int out_size) {
    const float* x     = (const float*)d_in[0];
    const int*   ei    = (const int*)  d_in[1];
    const int*   batch = (const int*)  d_in[2];
    const float* wl1   = (const float*)d_in[3];
    const float* bl1   = (const float*)d_in[4];
    const float* wr1   = (const float*)d_in[5];
    const float* br1   = (const float*)d_in[6];
    const float* att1  = (const float*)d_in[7];
    const float* bias1 = (const float*)d_in[8];
    const float* wl2   = (const float*)d_in[9];
    const float* bl2   = (const float*)d_in[10];
    const float* wr2   = (const float*)d_in[11];
    const float* br2   = (const float*)d_in[12];
    const float* att2  = (const float*)d_in[13];
    const float* bias2 = (const float*)d_in[14];
    const float* wm1   = (const float*)d_in[15];
    const float* bm1   = (const float*)d_in[16];
    const float* wm2   = (const float*)d_in[17];
    const float* bm2   = (const float*)d_in[18];
    const float* wm3   = (const float*)d_in[19];
    const float* bm3   = (const float*)d_in[20];
    const int* src = ei;
    const int* dst = ei + NEDGES;
    float* out = (float*)d_out;

    zero_kernel<<<(NNODES + 511) / 512, 512>>>();
    fusedA_kernel<<<GG + GH, 256>>>(x, wl1, bl1, wr1, br1, src, dst);
    edge1_fused_kernel<<<NNODES * 32 / 256, 256>>>(att1, bias1, wl2, bl2, wr2, br2);
    edge2_fused_kernel<<<(NNODES * 32 + 255) / 256, 256>>>(att2, bias2, batch);
    mlp_kernel<<<1, 256>>>(wm1, bm1, wm2, bm2, wm3, bm3, out);
}

// round 7
// speedup vs baseline: 1.1059x; 1.1059x over previous
#include <cuda_runtime.h>
#include <math.h>

#define NNODES 50000
#define NEDGES 1600000
#define ETOT   (NEDGES + NNODES)
#define INCH   64
#define HEADS  8
#define HID    16
#define HH     (HEADS*HID)   /* 128 */
#define NGRAPH 256
#define OUTC   32
#define CAP    128
#define GG     ((NNODES + 31) / 32)        /* gemm1 blocks = 1563 */
#define GH     ((ETOT + 255) / 256)        /* fill blocks  = 6446 */

// ---------------- scratch ----------------
__device__ __align__(16) float g_xl1[NNODES*HH];
__device__ __align__(16) float g_xr1[NNODES*HH];
__device__ __align__(16) float g_out1[NNODES*HH];
__device__ __align__(16) float g_xl2[NNODES*HID];
__device__ __align__(16) float g_xr2[NNODES*HID];
__device__ __align__(16) float g_pool[NGRAPH*HID];
__device__ __align__(16) float g_cnt[NGRAPH];
__device__ int g_count[NNODES];
__device__ int g_slot[(size_t)NNODES * CAP];

__device__ __forceinline__ float elu1f(float v) { return v > 0.f ? v : expm1f(v); }
__device__ __forceinline__ float lrelu(float v) { return fmaxf(v, 0.2f * v); }

// ---------------- zero: count + pool + cnt ----------------
__global__ void zero_kernel() {
    int i = blockIdx.x * blockDim.x + threadIdx.x;
    if (i < NNODES) g_count[i] = 0;
    if (i < NGRAPH * HID) g_pool[i] = 0.f;
    if (i < NGRAPH) g_cnt[i] = 0.f;
}

// ---------------- fused: gemm1 (first GG blocks) || bucket-fill (rest) ----------------
__global__ void __launch_bounds__(256) fusedA_kernel(
        const float* __restrict__ x,
        const float* __restrict__ wl, const float* __restrict__ bl,
        const float* __restrict__ wr, const float* __restrict__ br,
        const int* __restrict__ src, const int* __restrict__ dst) {
    if (blockIdx.x >= GG) {
        int e = (blockIdx.x - GG) * 256 + threadIdx.x;
        if (e < ETOT) {
            int s, d;
            if (e < NEDGES) { s = src[e]; d = dst[e]; } else { s = e - NEDGES; d = s; }
            int pos = atomicAdd(&g_count[d], 1);
            if (pos < CAP) g_slot[(size_t)d * CAP + pos] = s;
        }
        return;
    }
    __shared__ __align__(16) float xs[8][INCH];
    int tid = threadIdx.x;
    int c = tid & (HH - 1);
    const float* w = (tid < HH) ? wl : wr;
    float bias = (tid < HH) ? bl[c] : br[c];
    float wreg[INCH];
    #pragma unroll
    for (int k = 0; k < INCH; k++) wreg[k] = __ldg(&w[k * HH + c]);
    float* outp = (tid < HH) ? g_xl1 : g_xr1;
    int node0 = blockIdx.x * 32;
    for (int base = 0; base < 32; base += 8) {
        int n0 = node0 + base;
        __syncthreads();
        if (tid < 128) {
            int nn = tid >> 4, k4 = tid & 15;
            int g = n0 + nn;
            float4 v = (g < NNODES) ? ((const float4*)(x + (size_t)g * INCH))[k4]
                                    : make_float4(0.f, 0.f, 0.f, 0.f);
            ((float4*)&xs[nn][0])[k4] = v;
        }
        __syncthreads();
        float acc[8];
        #pragma unroll
        for (int j = 0; j < 8; j++) acc[j] = bias;
        #pragma unroll
        for (int k4 = 0; k4 < 16; k4++) {
            #pragma unroll
            for (int j = 0; j < 8; j++) {
                float4 xv = ((const float4*)&xs[j][0])[k4];
                acc[j] = fmaf(xv.x, wreg[4 * k4 + 0],
                         fmaf(xv.y, wreg[4 * k4 + 1],
                         fmaf(xv.z, wreg[4 * k4 + 2],
                         fmaf(xv.w, wreg[4 * k4 + 3], acc[j]))));
            }
        }
        #pragma unroll
        for (int j = 0; j < 8; j++) {
            int g = n0 + j;
            if (g < NNODES) outp[(size_t)g * HH + c] = acc[j];
        }
    }
}

// ---------------- conv1 fused edge pass (R5 form: no epilogue, low regs) ----------------
__device__ __forceinline__ float edge1_exp(float4 xv, float4 xr, float4 aw) {
    float p = lrelu(xv.x + xr.x) * aw.x + lrelu(xv.y + xr.y) * aw.y
            + lrelu(xv.z + xr.z) * aw.z + lrelu(xv.w + xr.w) * aw.w;
    p += __shfl_xor_sync(0xffffffffu, p, 1);
    p += __shfl_xor_sync(0xffffffffu, p, 2);
    return __expf(p);
}

__global__ void __launch_bounds__(256) edge1_fused_kernel(const float* __restrict__ att,
                                                          const float* __restrict__ bias) {
    int warp = (blockIdx.x * blockDim.x + threadIdx.x) >> 5;
    if (warp >= NNODES) return;
    int lane = threadIdx.x & 31;
    int d = warp;
    float4 xr = ((const float4*)(g_xr1 + (size_t)d * HH))[lane];
    float4 aw = __ldg(&((const float4*)att)[lane]);
    float4 acc = make_float4(0.f, 0.f, 0.f, 0.f);
    float den = 0.f;
    int deg = min(g_count[d], CAP);
    const int* slot = g_slot + (size_t)d * CAP;
    for (int blk = 0; blk < deg; blk += 32) {
        int nn = min(32, deg - blk);
        int myidx = (lane < nn) ? slot[blk + lane] : 0;
        int j = 0;
        for (; j + 3 < nn; j += 4) {
            int s0 = __shfl_sync(0xffffffffu, myidx, j);
            int s1 = __shfl_sync(0xffffffffu, myidx, j + 1);
            int s2 = __shfl_sync(0xffffffffu, myidx, j + 2);
            int s3 = __shfl_sync(0xffffffffu, myidx, j + 3);
            float4 x0 = ((const float4*)(g_xl1 + (size_t)s0 * HH))[lane];
            float4 x1 = ((const float4*)(g_xl1 + (size_t)s1 * HH))[lane];
            float4 x2 = ((const float4*)(g_xl1 + (size_t)s2 * HH))[lane];
            float4 x3 = ((const float4*)(g_xl1 + (size_t)s3 * HH))[lane];
            float e0 = edge1_exp(x0, xr, aw);
            float e1 = edge1_exp(x1, xr, aw);
            float e2 = edge1_exp(x2, xr, aw);
            float e3 = edge1_exp(x3, xr, aw);
            acc.x += e0 * x0.x + e1 * x1.x + e2 * x2.x + e3 * x3.x;
            acc.y += e0 * x0.y + e1 * x1.y + e2 * x2.y + e3 * x3.y;
            acc.z += e0 * x0.z + e1 * x1.z + e2 * x2.z + e3 * x3.z;
            acc.w += e0 * x0.w + e1 * x1.w + e2 * x2.w + e3 * x3.w;
            den += (e0 + e1) + (e2 + e3);
        }
        for (; j < nn; j++) {
            int s0 = __shfl_sync(0xffffffffu, myidx, j);
            float4 x0 = ((const float4*)(g_xl1 + (size_t)s0 * HH))[lane];
            float e0 = edge1_exp(x0, xr, aw);
            acc.x += e0 * x0.x; acc.y += e0 * x0.y; acc.z += e0 * x0.z; acc.w += e0 * x0.w;
            den += e0;
        }
    }
    float inv = 1.f / (den + 1e-16f);
    float4 b = __ldg(&((const float4*)bias)[lane]);
    float4 o;
    o.x = elu1f(fmaf(acc.x, inv, b.x));
    o.y = elu1f(fmaf(acc.y, inv, b.y));
    o.z = elu1f(fmaf(acc.z, inv, b.z));
    o.w = elu1f(fmaf(acc.w, inv, b.w));
    ((float4*)(g_out1 + (size_t)d * HH))[lane] = o;
}

// ---------------- conv2 node transform: warp per 2 nodes, register transpose-reduce ----------------
// wt LDS shared across the two nodes (halves smem traffic); no launch_bounds cap
// so r0[32]+r1[32] stay in registers (~90 regs, no spills).
__global__ void gemm2_kernel(const float* __restrict__ wl, const float* __restrict__ bl,
                             const float* __restrict__ wr, const float* __restrict__ br) {
    __shared__ __align__(16) float wt[32][HH];   // transposed [wl2|wr2], 16KB
    __shared__ float b2s[32];
    int tid = threadIdx.x;
    #pragma unroll
    for (int u = 0; u < 16; u++) {
        int idx = u * 256 + tid;                 // 4096 entries, coalesced-ish
        int j = idx >> 7, ch = idx & 127;
        wt[j][ch] = (j < HID) ? __ldg(&wl[ch * HID + j]) : __ldg(&wr[ch * HID + (j - HID)]);
    }
    if (tid < 32) b2s[tid] = (tid < HID) ? bl[tid] : br[tid - HID];
    __syncthreads();

    int warp = (blockIdx.x * 256 + tid) >> 5;    // 2 nodes per warp
    int lane = tid & 31;
    int d0 = warp * 2, d1 = warp * 2 + 1;
    if (d0 >= NNODES) return;
    bool has1 = (d1 < NNODES);
    float4 o0 = ((const float4*)(g_out1 + (size_t)d0 * HH))[lane];
    float4 o1 = has1 ? ((const float4*)(g_out1 + (size_t)d1 * HH))[lane]
                     : make_float4(0.f, 0.f, 0.f, 0.f);
    float r0[32], r1[32];
    #pragma unroll
    for (int j = 0; j < 32; j++) {
        float4 wv = ((const float4*)&wt[j][0])[lane];
        r0[j] = fmaf(o0.x, wv.x, fmaf(o0.y, wv.y, fmaf(o0.z, wv.z, o0.w * wv.w)));
        r1[j] = fmaf(o1.x, wv.x, fmaf(o1.y, wv.y, fmaf(o1.z, wv.z, o1.w * wv.w)));
    }
    // recursive-halving transpose-reduce (validated in R6): lane j ends with column j
    #pragma unroll
    for (int off = 16; off >= 1; off >>= 1) {
        bool upper = (lane & off) != 0;
        #pragma unroll
        for (int i = 0; i < off; i++) {
            float s0 = upper ? r0[i] : r0[i + off];
            float s1 = upper ? r1[i] : r1[i + off];
            float t0 = __shfl_xor_sync(0xffffffffu, s0, off);
            float t1 = __shfl_xor_sync(0xffffffffu, s1, off);
            r0[i] = (upper ? r0[i + off] : r0[i]) + t0;
            r1[i] = (upper ? r1[i + off] : r1[i]) + t1;
        }
    }
    float res0 = r0[0] + b2s[lane];
    float res1 = r1[0] + b2s[lane];
    if (lane < HID) {
        g_xl2[(size_t)d0 * HID + lane] = res0;
        if (has1) g_xl2[(size_t)d1 * HID + lane] = res1;
    } else {
        g_xr2[(size_t)d0 * HID + (lane - HID)] = res0;
        if (has1) g_xr2[(size_t)d1 * HID + (lane - HID)] = res1;
    }
}

// ---------------- conv2 fused edge pass + bias2 + ELU + mean-pool ----------------
__global__ void __launch_bounds__(256) edge2_fused_kernel(const float* __restrict__ att,
                                                          const float* __restrict__ bias,
                                                          const int* __restrict__ batch) {
    int warp = (blockIdx.x * blockDim.x + threadIdx.x) >> 5;
    if (warp >= NNODES) return;
    int lane = threadIdx.x & 31;
    int c = lane & 15;
    int sub = lane >> 4;
    int d = warp;
    float xr = g_xr2[(size_t)d * HID + c];
    float aw = __ldg(&att[c]);
    float acc = 0.f, den = 0.f;
    int deg = min(g_count[d], CAP);
    const int* slot = g_slot + (size_t)d * CAP;
    for (int blk = 0; blk < deg; blk += 32) {
        int nn = min(32, deg - blk);
        int myidx = (lane < nn) ? slot[blk + lane] : 0;
        int j = 0;
        for (; j + 3 < nn; j += 4) {
            int s0 = __shfl_sync(0xffffffffu, myidx, j + sub);
            int s1 = __shfl_sync(0xffffffffu, myidx, j + 2 + sub);
            float xl0 = g_xl2[(size_t)s0 * HID + c];
            float xl1 = g_xl2[(size_t)s1 * HID + c];
            float p0 = lrelu(xl0 + xr) * aw;
            float p1 = lrelu(xl1 + xr) * aw;
            p0 += __shfl_xor_sync(0xffffffffu, p0, 1);
            p1 += __shfl_xor_sync(0xffffffffu, p1, 1);
            p0 += __shfl_xor_sync(0xffffffffu, p0, 2);
            p1 += __shfl_xor_sync(0xffffffffu, p1, 2);
            p0 += __shfl_xor_sync(0xffffffffu, p0, 4);
            p1 += __shfl_xor_sync(0xffffffffu, p1, 4);
            p0 += __shfl_xor_sync(0xffffffffu, p0, 8);
            p1 += __shfl_xor_sync(0xffffffffu, p1, 8);
            float e0 = __expf(p0), e1 = __expf(p1);
            acc += e0 * xl0 + e1 * xl1;
            den += e0 + e1;
        }
        for (; j < nn; j += 2) {
            int take1 = (j + 1 < nn);
            int idx = j + (take1 ? sub : 0);
            int s = __shfl_sync(0xffffffffu, myidx, idx);
            float xl = g_xl2[(size_t)s * HID + c];
            float p = lrelu(xl + xr) * aw;
            p += __shfl_xor_sync(0xffffffffu, p, 1);
            p += __shfl_xor_sync(0xffffffffu, p, 2);
            p += __shfl_xor_sync(0xffffffffu, p, 4);
            p += __shfl_xor_sync(0xffffffffu, p, 8);
            bool ok = take1 || (sub == 0);
            float ex = ok ? __expf(p) : 0.f;
            acc += ex * xl;
            den += ex;
        }
    }
    acc += __shfl_xor_sync(0xffffffffu, acc, 16);
    den += __shfl_xor_sync(0xffffffffu, den, 16);
    if (sub == 0) {
        float o = elu1f(acc / (den + 1e-16f) + __ldg(&bias[c]));
        int b = batch[d];
        atomicAdd(&g_pool[b * HID + c], o);
        if (c == 0) atomicAdd(&g_cnt[b], 1.f);
    }
}

// ---------------- final MLP ----------------
__global__ void mlp_kernel(const float* __restrict__ w1, const float* __restrict__ b1,
                           const float* __restrict__ w2, const float* __restrict__ b2,
                           const float* __restrict__ w3, const float* __restrict__ b3,
                           float* __restrict__ out) {
    __shared__ float s1[HID * 32], sb1[32];
    __shared__ float s2[32 * HID], sb2[HID];
    __shared__ float s3[HID * 32], sb3[32];
    int tid = threadIdx.x;
    for (int i = tid; i < HID * 32; i += 256) s1[i] = w1[i];
    for (int i = tid; i < 32 * HID; i += 256) s2[i] = w2[i];
    for (int i = tid; i < HID * 32; i += 256) s3[i] = w3[i];
    if (tid < 32) { sb1[tid] = b1[tid]; sb3[tid] = b3[tid]; }
    if (tid < HID) sb2[tid] = b2[tid];
    __syncthreads();
    int b = tid;
    float cnt = fmaxf(g_cnt[b], 1.f);
    float h[HID];
    #pragma unroll
    for (int c = 0; c < HID; c++) h[c] = g_pool[b * HID + c] / cnt;
    float t1[32];
    #pragma unroll
    for (int j = 0; j < 32; j++) {
        float s = sb1[j];
        #pragma unroll
        for (int k = 0; k < HID; k++) s += h[k] * s1[k * 32 + j];
        t1[j] = elu1f(s);
    }
    float t2[HID];
    #pragma unroll
    for (int j = 0; j < HID; j++) {
        float s = sb2[j];
        #pragma unroll
        for (int k = 0; k < 32; k++) s += t1[k] * s2[k * HID + j];
        t2[j] = elu1f(s);
    }
    #pragma unroll
    for (int j = 0; j < 32; j++) {
        float s = sb3[j];
        #pragma unroll
        for (int k = 0; k < HID; k++) s += t2[k] * s3[k * 32 + j];
        out[b * 32 + j] = s;
    }
}

// ---------------- launch ----------------
extern "C" void kernel_launch(void* const* d_in, const int* in_sizes, int n_in,
                              void* d_out, int out_size) {
    const float* x     = (const float*)d_in[0];
    const int*   ei    = (const int*)  d_in[1];
    const int*   batch = (const int*)  d_in[2];
    const float* wl1   = (const float*)d_in[3];
    const float* bl1   = (const float*)d_in[4];
    const float* wr1   = (const float*)d_in[5];
    const float* br1   = (const float*)d_in[6];
    const float* att1  = (const float*)d_in[7];
    const float* bias1 = (const float*)d_in[8];
    const float* wl2   = (const float*)d_in[9];
    const float* bl2   = (const float*)d_in[10];
    const float* wr2   = (const float*)d_in[11];
    const float* br2   = (const float*)d_in[12];
    const float* att2  = (const float*)d_in[13];
    const float* bias2 = (const float*)d_in[14];
    const float* wm1   = (const float*)d_in[15];
    const float* bm1   = (const float*)d_in[16];
    const float* wm2   = (const float*)d_in[17];
    const float* bm2   = (const float*)d_in[18];
    const float* wm3   = (const float*)d_in[19];
    const float* bm3   = (const float*)d_in[20];
    const int* src = ei;
    const int* dst = ei + NEDGES;
    float* out = (float*)d_out;

    zero_kernel<<<(NNODES + 511) / 512, 512>>>();
    fusedA_kernel<<<GG + GH, 256>>>(x, wl1, bl1, wr1, br1, src, dst);
    edge1_fused_kernel<<<(NNODES * 32 + 255) / 256, 256>>>(att1, bias1);
    gemm2_kernel<<<(NNODES / 2 * 32 + 255) / 256, 256>>>(wl2, bl2, wr2, br2);
    edge2_fused_kernel<<<(NNODES * 32 + 255) / 256, 256>>>(att2, bias2, batch);
    mlp_kernel<<<1, 256>>>(wm1, bm1, wm2, bm2, wm3, bm3, out);
}

// round 8
// speedup vs baseline: 1.2133x; 1.0972x over previous
#include <cuda_runtime.h>
#include <math.h>

#define NNODES 50000
#define NEDGES 1600000
#define ETOT   (NEDGES + NNODES)
#define INCH   64
#define HEADS  8
#define HID    16
#define HH     (HEADS*HID)   /* 128 */
#define NGRAPH 256
#define OUTC   32
#define CAP    128
#define GG     ((NNODES + 31) / 32)        /* gemm1 blocks = 1563 */
#define GH     ((ETOT + 255) / 256)        /* fill blocks  = 6446 */
#define WSTR   132                          /* padded wt row stride (floats) */

// ---------------- scratch ----------------
__device__ __align__(16) float g_xl1[NNODES*HH];
__device__ __align__(16) float g_xr1[NNODES*HH];
__device__ __align__(16) float g_out1[NNODES*HH];
__device__ __align__(16) float g_xl2[NNODES*HID];
__device__ __align__(16) float g_xr2[NNODES*HID];
__device__ __align__(16) float g_pool[NGRAPH*HID];
__device__ __align__(16) float g_cnt[NGRAPH];
__device__ int g_count[NNODES];
__device__ int g_slot[(size_t)NNODES * CAP];

__device__ __forceinline__ float elu1f(float v) { return v > 0.f ? v : expm1f(v); }
__device__ __forceinline__ float lrelu(float v) { return fmaxf(v, 0.2f * v); }

// ---------------- zero: count + pool + cnt ----------------
__global__ void zero_kernel() {
    int i = blockIdx.x * blockDim.x + threadIdx.x;
    if (i < NNODES) g_count[i] = 0;
    if (i < NGRAPH * HID) g_pool[i] = 0.f;
    if (i < NGRAPH) g_cnt[i] = 0.f;
}

// ---------------- fused: gemm1 (first GG blocks) || bucket-fill (rest) ----------------
__global__ void __launch_bounds__(256) fusedA_kernel(
        const float* __restrict__ x,
        const float* __restrict__ wl, const float* __restrict__ bl,
        const float* __restrict__ wr, const float* __restrict__ br,
        const int* __restrict__ src, const int* __restrict__ dst) {
    if (blockIdx.x >= GG) {
        int e = (blockIdx.x - GG) * 256 + threadIdx.x;
        if (e < ETOT) {
            int s, d;
            if (e < NEDGES) { s = src[e]; d = dst[e]; } else { s = e - NEDGES; d = s; }
            int pos = atomicAdd(&g_count[d], 1);
            if (pos < CAP) g_slot[(size_t)d * CAP + pos] = s;
        }
        return;
    }
    __shared__ __align__(16) float xs[8][INCH];
    int tid = threadIdx.x;
    int c = tid & (HH - 1);
    const float* w = (tid < HH) ? wl : wr;
    float bias = (tid < HH) ? bl[c] : br[c];
    float wreg[INCH];
    #pragma unroll
    for (int k = 0; k < INCH; k++) wreg[k] = __ldg(&w[k * HH + c]);
    float* outp = (tid < HH) ? g_xl1 : g_xr1;
    int node0 = blockIdx.x * 32;
    for (int base = 0; base < 32; base += 8) {
        int n0 = node0 + base;
        __syncthreads();
        if (tid < 128) {
            int nn = tid >> 4, k4 = tid & 15;
            int g = n0 + nn;
            float4 v = (g < NNODES) ? ((const float4*)(x + (size_t)g * INCH))[k4]
                                    : make_float4(0.f, 0.f, 0.f, 0.f);
            ((float4*)&xs[nn][0])[k4] = v;
        }
        __syncthreads();
        float acc[8];
        #pragma unroll
        for (int j = 0; j < 8; j++) acc[j] = bias;
        #pragma unroll
        for (int k4 = 0; k4 < 16; k4++) {
            #pragma unroll
            for (int j = 0; j < 8; j++) {
                float4 xv = ((const float4*)&xs[j][0])[k4];
                acc[j] = fmaf(xv.x, wreg[4 * k4 + 0],
                         fmaf(xv.y, wreg[4 * k4 + 1],
                         fmaf(xv.z, wreg[4 * k4 + 2],
                         fmaf(xv.w, wreg[4 * k4 + 3], acc[j]))));
            }
        }
        #pragma unroll
        for (int j = 0; j < 8; j++) {
            int g = n0 + j;
            if (g < NNODES) outp[(size_t)g * HH + c] = acc[j];
        }
    }
}

// ---------------- conv1 fused edge pass ----------------
__device__ __forceinline__ float edge1_exp(float4 xv, float4 xr, float4 aw) {
    float p = lrelu(xv.x + xr.x) * aw.x + lrelu(xv.y + xr.y) * aw.y
            + lrelu(xv.z + xr.z) * aw.z + lrelu(xv.w + xr.w) * aw.w;
    p += __shfl_xor_sync(0xffffffffu, p, 1);
    p += __shfl_xor_sync(0xffffffffu, p, 2);
    return __expf(p);
}

__global__ void __launch_bounds__(256) edge1_fused_kernel(const float* __restrict__ att,
                                                          const float* __restrict__ bias) {
    int warp = (blockIdx.x * blockDim.x + threadIdx.x) >> 5;
    if (warp >= NNODES) return;
    int lane = threadIdx.x & 31;
    int d = warp;
    float4 xr = ((const float4*)(g_xr1 + (size_t)d * HH))[lane];
    float4 aw = __ldg(&((const float4*)att)[lane]);
    float4 acc = make_float4(0.f, 0.f, 0.f, 0.f);
    float den = 0.f;
    int deg = min(g_count[d], CAP);
    const int* slot = g_slot + (size_t)d * CAP;
    for (int blk = 0; blk < deg; blk += 32) {
        int nn = min(32, deg - blk);
        int myidx = (lane < nn) ? slot[blk + lane] : 0;
        int j = 0;
        for (; j + 3 < nn; j += 4) {
            int s0 = __shfl_sync(0xffffffffu, myidx, j);
            int s1 = __shfl_sync(0xffffffffu, myidx, j + 1);
            int s2 = __shfl_sync(0xffffffffu, myidx, j + 2);
            int s3 = __shfl_sync(0xffffffffu, myidx, j + 3);
            float4 x0 = ((const float4*)(g_xl1 + (size_t)s0 * HH))[lane];
            float4 x1 = ((const float4*)(g_xl1 + (size_t)s1 * HH))[lane];
            float4 x2 = ((const float4*)(g_xl1 + (size_t)s2 * HH))[lane];
            float4 x3 = ((const float4*)(g_xl1 + (size_t)s3 * HH))[lane];
            float e0 = edge1_exp(x0, xr, aw);
            float e1 = edge1_exp(x1, xr, aw);
            float e2 = edge1_exp(x2, xr, aw);
            float e3 = edge1_exp(x3, xr, aw);
            acc.x += e0 * x0.x + e1 * x1.x + e2 * x2.x + e3 * x3.x;
            acc.y += e0 * x0.y + e1 * x1.y + e2 * x2.y + e3 * x3.y;
            acc.z += e0 * x0.z + e1 * x1.z + e2 * x2.z + e3 * x3.z;
            acc.w += e0 * x0.w + e1 * x1.w + e2 * x2.w + e3 * x3.w;
            den += (e0 + e1) + (e2 + e3);
        }
        for (; j < nn; j++) {
            int s0 = __shfl_sync(0xffffffffu, myidx, j);
            float4 x0 = ((const float4*)(g_xl1 + (size_t)s0 * HH))[lane];
            float e0 = edge1_exp(x0, xr, aw);
            acc.x += e0 * x0.x; acc.y += e0 * x0.y; acc.z += e0 * x0.z; acc.w += e0 * x0.w;
            den += e0;
        }
    }
    float inv = 1.f / (den + 1e-16f);
    float4 b = __ldg(&((const float4*)bias)[lane]);
    float4 o;
    o.x = elu1f(fmaf(acc.x, inv, b.x));
    o.y = elu1f(fmaf(acc.y, inv, b.y));
    o.z = elu1f(fmaf(acc.z, inv, b.z));
    o.w = elu1f(fmaf(acc.w, inv, b.w));
    ((float4*)(g_out1 + (size_t)d * HH))[lane] = o;
}

// ---------------- conv2 node transform: register-tiled GEMM ----------------
// Block: 128 nodes x 32 cols. Thread: 4 nodes x 4 cols (acc[4][4]).
// ng = tid>>3 (nodes ng+32i), cg = tid&7 (cols cg+8j, strided -> conflict-free LDS).
// x read directly from g_out1 (L1-resident tile), w^T staged in padded smem.
__global__ void __launch_bounds__(256) gemm2_kernel(
        const float* __restrict__ wl, const float* __restrict__ bl,
        const float* __restrict__ wr, const float* __restrict__ br) {
    __shared__ __align__(16) float wt[32 * WSTR];   // wt[c][k], padded rows
    __shared__ float b2s[32];
    int tid = threadIdx.x;
    #pragma unroll
    for (int u = 0; u < 16; u++) {
        int idx = u * 256 + tid;                    // 4096 entries
        int c = idx >> 7, k = idx & 127;
        wt[c * WSTR + k] = (c < HID) ? __ldg(&wl[k * HID + c])
                                     : __ldg(&wr[k * HID + (c - HID)]);
    }
    if (tid < 32) b2s[tid] = (tid < HID) ? bl[tid] : br[tid - HID];
    __syncthreads();

    int node0 = blockIdx.x * 128;
    int ng = tid >> 3;          // 0..31
    int cg = tid & 7;           // 0..7
    int n[4];
    const float4* xp[4];
    #pragma unroll
    for (int i = 0; i < 4; i++) {
        n[i] = node0 + ng + 32 * i;
        int nc = min(n[i], NNODES - 1);
        xp[i] = (const float4*)(g_out1 + (size_t)nc * HH);
    }
    const float4* wp[4];
    #pragma unroll
    for (int j = 0; j < 4; j++) wp[j] = (const float4*)(wt + (cg + 8 * j) * WSTR);

    float acc[4][4];
    #pragma unroll
    for (int i = 0; i < 4; i++)
        #pragma unroll
        for (int j = 0; j < 4; j++) acc[i][j] = 0.f;

    #pragma unroll 4
    for (int k4 = 0; k4 < 32; k4++) {
        float4 xv[4], wv[4];
        #pragma unroll
        for (int i = 0; i < 4; i++) xv[i] = xp[i][k4];
        #pragma unroll
        for (int j = 0; j < 4; j++) wv[j] = wp[j][k4];
        #pragma unroll
        for (int i = 0; i < 4; i++)
            #pragma unroll
            for (int j = 0; j < 4; j++)
                acc[i][j] = fmaf(xv[i].x, wv[j].x,
                            fmaf(xv[i].y, wv[j].y,
                            fmaf(xv[i].z, wv[j].z,
                            fmaf(xv[i].w, wv[j].w, acc[i][j]))));
    }

    #pragma unroll
    for (int i = 0; i < 4; i++) {
        if (n[i] >= NNODES) continue;
        #pragma unroll
        for (int j = 0; j < 4; j++) {
            int c = cg + 8 * j;
            float res = acc[i][j] + b2s[c];
            if (c < HID) g_xl2[(size_t)n[i] * HID + c] = res;
            else         g_xr2[(size_t)n[i] * HID + (c - HID)] = res;
        }
    }
}

// ---------------- conv2 fused edge pass + bias2 + ELU + mean-pool ----------------
__global__ void __launch_bounds__(256) edge2_fused_kernel(const float* __restrict__ att,
                                                          const float* __restrict__ bias,
                                                          const int* __restrict__ batch) {
    int warp = (blockIdx.x * blockDim.x + threadIdx.x) >> 5;
    if (warp >= NNODES) return;
    int lane = threadIdx.x & 31;
    int c = lane & 15;
    int sub = lane >> 4;
    int d = warp;
    float xr = g_xr2[(size_t)d * HID + c];
    float aw = __ldg(&att[c]);
    float acc = 0.f, den = 0.f;
    int deg = min(g_count[d], CAP);
    const int* slot = g_slot + (size_t)d * CAP;
    for (int blk = 0; blk < deg; blk += 32) {
        int nn = min(32, deg - blk);
        int myidx = (lane < nn) ? slot[blk + lane] : 0;
        int j = 0;
        for (; j + 3 < nn; j += 4) {
            int s0 = __shfl_sync(0xffffffffu, myidx, j + sub);
            int s1 = __shfl_sync(0xffffffffu, myidx, j + 2 + sub);
            float xl0 = g_xl2[(size_t)s0 * HID + c];
            float xl1 = g_xl2[(size_t)s1 * HID + c];
            float p0 = lrelu(xl0 + xr) * aw;
            float p1 = lrelu(xl1 + xr) * aw;
            p0 += __shfl_xor_sync(0xffffffffu, p0, 1);
            p1 += __shfl_xor_sync(0xffffffffu, p1, 1);
            p0 += __shfl_xor_sync(0xffffffffu, p0, 2);
            p1 += __shfl_xor_sync(0xffffffffu, p1, 2);
            p0 += __shfl_xor_sync(0xffffffffu, p0, 4);
            p1 += __shfl_xor_sync(0xffffffffu, p1, 4);
            p0 += __shfl_xor_sync(0xffffffffu, p0, 8);
            p1 += __shfl_xor_sync(0xffffffffu, p1, 8);
            float e0 = __expf(p0), e1 = __expf(p1);
            acc += e0 * xl0 + e1 * xl1;
            den += e0 + e1;
        }
        for (; j < nn; j += 2) {
            int take1 = (j + 1 < nn);
            int idx = j + (take1 ? sub : 0);
            int s = __shfl_sync(0xffffffffu, myidx, idx);
            float xl = g_xl2[(size_t)s * HID + c];
            float p = lrelu(xl + xr) * aw;
            p += __shfl_xor_sync(0xffffffffu, p, 1);
            p += __shfl_xor_sync(0xffffffffu, p, 2);
            p += __shfl_xor_sync(0xffffffffu, p, 4);
            p += __shfl_xor_sync(0xffffffffu, p, 8);
            bool ok = take1 || (sub == 0);
            float ex = ok ? __expf(p) : 0.f;
            acc += ex * xl;
            den += ex;
        }
    }
    acc += __shfl_xor_sync(0xffffffffu, acc, 16);
    den += __shfl_xor_sync(0xffffffffu, den, 16);
    if (sub == 0) {
        float o = elu1f(acc / (den + 1e-16f) + __ldg(&bias[c]));
        int b = batch[d];
        atomicAdd(&g_pool[b * HID + c], o);
        if (c == 0) atomicAdd(&g_cnt[b], 1.f);
    }
}

// ---------------- final MLP ----------------
__global__ void mlp_kernel(const float* __restrict__ w1, const float* __restrict__ b1,
                           const float* __restrict__ w2, const float* __restrict__ b2,
                           const float* __restrict__ w3, const float* __restrict__ b3,
                           float* __restrict__ out) {
    __shared__ float s1[HID * 32], sb1[32];
    __shared__ float s2[32 * HID], sb2[HID];
    __shared__ float s3[HID * 32], sb3[32];
    int tid = threadIdx.x;
    for (int i = tid; i < HID * 32; i += 256) s1[i] = w1[i];
    for (int i = tid; i < 32 * HID; i += 256) s2[i] = w2[i];
    for (int i = tid; i < HID * 32; i += 256) s3[i] = w3[i];
    if (tid < 32) { sb1[tid] = b1[tid]; sb3[tid] = b3[tid]; }
    if (tid < HID) sb2[tid] = b2[tid];
    __syncthreads();
    int b = tid;
    float cnt = fmaxf(g_cnt[b], 1.f);
    float h[HID];
    #pragma unroll
    for (int c = 0; c < HID; c++) h[c] = g_pool[b * HID + c] / cnt;
    float t1[32];
    #pragma unroll
    for (int j = 0; j < 32; j++) {
        float s = sb1[j];
        #pragma unroll
        for (int k = 0; k < HID; k++) s += h[k] * s1[k * 32 + j];
        t1[j] = elu1f(s);
    }
    float t2[HID];
    #pragma unroll
    for (int j = 0; j < HID; j++) {
        float s = sb2[j];
        #pragma unroll
        for (int k = 0; k < 32; k++) s += t1[k] * s2[k * HID + j];
        t2[j] = elu1f(s);
    }
    #pragma unroll
    for (int j = 0; j < 32; j++) {
        float s = sb3[j];
        #pragma unroll
        for (int k = 0; k < HID; k++) s += t2[k] * s3[k * 32 + j];
        out[b * 32 + j] = s;
    }
}

// ---------------- launch ----------------
extern "C" void kernel_launch(void* const* d_in, const int* in_sizes, int n_in,
                              void* d_out, int out_size) {
    const float* x     = (const float*)d_in[0];
    const int*   ei    = (const int*)  d_in[1];
    const int*   batch = (const int*)  d_in[2];
    const float* wl1   = (const float*)d_in[3];
    const float* bl1   = (const float*)d_in[4];
    const float* wr1   = (const float*)d_in[5];
    const float* br1   = (const float*)d_in[6];
    const float* att1  = (const float*)d_in[7];
    const float* bias1 = (const float*)d_in[8];
    const float* wl2   = (const float*)d_in[9];
    const float* bl2   = (const float*)d_in[10];
    const float* wr2   = (const float*)d_in[11];
    const float* br2   = (const float*)d_in[12];
    const float* att2  = (const float*)d_in[13];
    const float* bias2 = (const float*)d_in[14];
    const float* wm1   = (const float*)d_in[15];
    const float* bm1   = (const float*)d_in[16];
    const float* wm2   = (const float*)d_in[17];
    const float* bm2   = (const float*)d_in[18];
    const float* wm3   = (const float*)d_in[19];
    const float* bm3   = (const float*)d_in[20];
    const int* src = ei;
    const int* dst = ei + NEDGES;
    float* out = (float*)d_out;

    zero_kernel<<<(NNODES + 511) / 512, 512>>>();
    fusedA_kernel<<<GG + GH, 256>>>(x, wl1, bl1, wr1, br1, src, dst);
    edge1_fused_kernel<<<(NNODES * 32 + 255) / 256, 256>>>(att1, bias1);
    gemm2_kernel<<<(NNODES + 127) / 128, 256>>>(wl2, bl2, wr2, br2);
    edge2_fused_kernel<<<(NNODES * 32 + 255) / 256, 256>>>(att2, bias2, batch);
    mlp_kernel<<<1, 256>>>(wm1, bm1, wm2, bm2, wm3, bm3, out);
}

// round 9
// speedup vs baseline: 1.2249x; 1.0095x over previous
#include <cuda_runtime.h>
#include <math.h>

#define NNODES 50000
#define NEDGES 1600000
#define ETOT   (NEDGES + NNODES)
#define INCH   64
#define HEADS  8
#define HID    16
#define HH     (HEADS*HID)   /* 128 */
#define NGRAPH 256
#define OUTC   32
#define CAP    128
#define GG     ((NNODES + 31) / 32)        /* gemm1 blocks = 1563 */
#define GH     ((ETOT + 255) / 256)        /* fill blocks  = 6446 */
#define WSTR   132

// ---------------- scratch ----------------
__device__ __align__(16) float g_xl1[NNODES*HH];
__device__ __align__(16) float g_xr1[NNODES*HH];
__device__ __align__(16) float g_out1[NNODES*HH];
__device__ __align__(16) float g_xl2[NNODES*HID];
__device__ __align__(16) float g_xr2[NNODES*HID];
__device__ __align__(16) float g_pool[NGRAPH*HID];
__device__ __align__(16) float g_cnt[NGRAPH];
__device__ int g_count[NNODES];
__device__ int g_slot[(size_t)NNODES * CAP];

__device__ __forceinline__ float elu1f(float v) { return v > 0.f ? v : expm1f(v); }
__device__ __forceinline__ float lrelu(float v) { return fmaxf(v, 0.2f * v); }

__device__ __forceinline__ void red_add_v4(float* p, float4 v) {
    unsigned long long gp = (unsigned long long)__cvta_generic_to_global((void*)p);
    asm volatile("red.global.add.v4.f32 [%0], {%1,%2,%3,%4};"
                 :: "l"(gp), "f"(v.x), "f"(v.y), "f"(v.z), "f"(v.w) : "memory");
}

// ---------------- zero: count + pool + cnt ----------------
__global__ void zero_kernel() {
    int i = blockIdx.x * blockDim.x + threadIdx.x;
    if (i < NNODES) g_count[i] = 0;
    if (i < NGRAPH * HID) g_pool[i] = 0.f;
    if (i < NGRAPH) g_cnt[i] = 0.f;
}

// ---------------- fused: gemm1 (first GG blocks) || bucket-fill (rest) ----------------
__global__ void __launch_bounds__(256) fusedA_kernel(
        const float* __restrict__ x,
        const float* __restrict__ wl, const float* __restrict__ bl,
        const float* __restrict__ wr, const float* __restrict__ br,
        const int* __restrict__ src, const int* __restrict__ dst) {
    if (blockIdx.x >= GG) {
        int e = (blockIdx.x - GG) * 256 + threadIdx.x;
        if (e < ETOT) {
            int s, d;
            if (e < NEDGES) { s = src[e]; d = dst[e]; } else { s = e - NEDGES; d = s; }
            int pos = atomicAdd(&g_count[d], 1);
            if (pos < CAP) g_slot[(size_t)d * CAP + pos] = s;
        }
        return;
    }
    __shared__ __align__(16) float xs[8][INCH];
    int tid = threadIdx.x;
    int c = tid & (HH - 1);
    const float* w = (tid < HH) ? wl : wr;
    float bias = (tid < HH) ? bl[c] : br[c];
    float wreg[INCH];
    #pragma unroll
    for (int k = 0; k < INCH; k++) wreg[k] = __ldg(&w[k * HH + c]);
    float* outp = (tid < HH) ? g_xl1 : g_xr1;
    int node0 = blockIdx.x * 32;
    for (int base = 0; base < 32; base += 8) {
        int n0 = node0 + base;
        __syncthreads();
        if (tid < 128) {
            int nn = tid >> 4, k4 = tid & 15;
            int g = n0 + nn;
            float4 v = (g < NNODES) ? ((const float4*)(x + (size_t)g * INCH))[k4]
                                    : make_float4(0.f, 0.f, 0.f, 0.f);
            ((float4*)&xs[nn][0])[k4] = v;
        }
        __syncthreads();
        float acc[8];
        #pragma unroll
        for (int j = 0; j < 8; j++) acc[j] = bias;
        #pragma unroll
        for (int k4 = 0; k4 < 16; k4++) {
            #pragma unroll
            for (int j = 0; j < 8; j++) {
                float4 xv = ((const float4*)&xs[j][0])[k4];
                acc[j] = fmaf(xv.x, wreg[4 * k4 + 0],
                         fmaf(xv.y, wreg[4 * k4 + 1],
                         fmaf(xv.z, wreg[4 * k4 + 2],
                         fmaf(xv.w, wreg[4 * k4 + 3], acc[j]))));
            }
        }
        #pragma unroll
        for (int j = 0; j < 8; j++) {
            int g = n0 + j;
            if (g < NNODES) outp[(size_t)g * HH + c] = acc[j];
        }
    }
}

// ---------------- conv1 fused edge pass: warp per node, 8-deep gather pipeline ----------------
__device__ __forceinline__ float edge1_exp(float4 xv, float4 xr, float4 aw) {
    float p = lrelu(xv.x + xr.x) * aw.x + lrelu(xv.y + xr.y) * aw.y
            + lrelu(xv.z + xr.z) * aw.z + lrelu(xv.w + xr.w) * aw.w;
    p += __shfl_xor_sync(0xffffffffu, p, 1);
    p += __shfl_xor_sync(0xffffffffu, p, 2);
    return __expf(p);
}

__global__ void __launch_bounds__(256) edge1_fused_kernel(const float* __restrict__ att,
                                                          const float* __restrict__ bias) {
    int warp = (blockIdx.x * blockDim.x + threadIdx.x) >> 5;
    if (warp >= NNODES) return;
    int lane = threadIdx.x & 31;
    int d = warp;
    float4 xr = ((const float4*)(g_xr1 + (size_t)d * HH))[lane];
    float4 aw = __ldg(&((const float4*)att)[lane]);
    float4 acc = make_float4(0.f, 0.f, 0.f, 0.f);
    float den = 0.f;
    int deg = min(g_count[d], CAP);
    const int* slot = g_slot + (size_t)d * CAP;
    for (int blk = 0; blk < deg; blk += 32) {
        int nn = min(32, deg - blk);
        int myidx = (lane < nn) ? slot[blk + lane] : 0;
        int j = 0;
        for (; j + 7 < nn; j += 8) {
            int s[8];
            float4 xv[8];
            #pragma unroll
            for (int u = 0; u < 8; u++) s[u] = __shfl_sync(0xffffffffu, myidx, j + u);
            #pragma unroll
            for (int u = 0; u < 8; u++)
                xv[u] = ((const float4*)(g_xl1 + (size_t)s[u] * HH))[lane];
            float e[8];
            #pragma unroll
            for (int u = 0; u < 8; u++) e[u] = edge1_exp(xv[u], xr, aw);
            #pragma unroll
            for (int u = 0; u < 8; u++) {
                acc.x += e[u] * xv[u].x;
                acc.y += e[u] * xv[u].y;
                acc.z += e[u] * xv[u].z;
                acc.w += e[u] * xv[u].w;
                den += e[u];
            }
        }
        for (; j < nn; j++) {
            int s0 = __shfl_sync(0xffffffffu, myidx, j);
            float4 x0 = ((const float4*)(g_xl1 + (size_t)s0 * HH))[lane];
            float e0 = edge1_exp(x0, xr, aw);
            acc.x += e0 * x0.x; acc.y += e0 * x0.y; acc.z += e0 * x0.z; acc.w += e0 * x0.w;
            den += e0;
        }
    }
    float inv = 1.f / (den + 1e-16f);
    float4 b = __ldg(&((const float4*)bias)[lane]);
    float4 o;
    o.x = elu1f(fmaf(acc.x, inv, b.x));
    o.y = elu1f(fmaf(acc.y, inv, b.y));
    o.z = elu1f(fmaf(acc.z, inv, b.z));
    o.w = elu1f(fmaf(acc.w, inv, b.w));
    ((float4*)(g_out1 + (size_t)d * HH))[lane] = o;
}

// ---------------- conv2 node transform: register-tiled GEMM (R8) ----------------
__global__ void __launch_bounds__(256) gemm2_kernel(
        const float* __restrict__ wl, const float* __restrict__ bl,
        const float* __restrict__ wr, const float* __restrict__ br) {
    __shared__ __align__(16) float wt[32 * WSTR];
    __shared__ float b2s[32];
    int tid = threadIdx.x;
    #pragma unroll
    for (int u = 0; u < 16; u++) {
        int idx = u * 256 + tid;
        int c = idx >> 7, k = idx & 127;
        wt[c * WSTR + k] = (c < HID) ? __ldg(&wl[k * HID + c])
                                     : __ldg(&wr[k * HID + (c - HID)]);
    }
    if (tid < 32) b2s[tid] = (tid < HID) ? bl[tid] : br[tid - HID];
    __syncthreads();

    int node0 = blockIdx.x * 128;
    int ng = tid >> 3;
    int cg = tid & 7;
    int n[4];
    const float4* xp[4];
    #pragma unroll
    for (int i = 0; i < 4; i++) {
        n[i] = node0 + ng + 32 * i;
        int nc = min(n[i], NNODES - 1);
        xp[i] = (const float4*)(g_out1 + (size_t)nc * HH);
    }
    const float4* wp[4];
    #pragma unroll
    for (int j = 0; j < 4; j++) wp[j] = (const float4*)(wt + (cg + 8 * j) * WSTR);

    float acc[4][4];
    #pragma unroll
    for (int i = 0; i < 4; i++)
        #pragma unroll
        for (int j = 0; j < 4; j++) acc[i][j] = 0.f;

    #pragma unroll 4
    for (int k4 = 0; k4 < 32; k4++) {
        float4 xv[4], wv[4];
        #pragma unroll
        for (int i = 0; i < 4; i++) xv[i] = xp[i][k4];
        #pragma unroll
        for (int j = 0; j < 4; j++) wv[j] = wp[j][k4];
        #pragma unroll
        for (int i = 0; i < 4; i++)
            #pragma unroll
            for (int j = 0; j < 4; j++)
                acc[i][j] = fmaf(xv[i].x, wv[j].x,
                            fmaf(xv[i].y, wv[j].y,
                            fmaf(xv[i].z, wv[j].z,
                            fmaf(xv[i].w, wv[j].w, acc[i][j]))));
    }

    #pragma unroll
    for (int i = 0; i < 4; i++) {
        if (n[i] >= NNODES) continue;
        #pragma unroll
        for (int j = 0; j < 4; j++) {
            int c = cg + 8 * j;
            float res = acc[i][j] + b2s[c];
            if (c < HID) g_xl2[(size_t)n[i] * HID + c] = res;
            else         g_xr2[(size_t)n[i] * HID + (c - HID)] = res;
        }
    }
}

// ---------------- conv2 edge pass: 8 edges per warp-iteration ----------------
// lane: g = lane>>2 (edge group 0..7), c4 = lane&3 (channel quad of 16 ch).
// Per iter: 8 edges processed in parallel, each by 4 lanes (float4 gather + dot
// + 2 shfl). Cross-group reduce once per node; pool via red.v4. Exp masked by
// predicate (no divergent shfl: all shuffles execute on all lanes).
__global__ void __launch_bounds__(256) edge2_fused_kernel(const float* __restrict__ att,
                                                          const float* __restrict__ bias,
                                                          const int* __restrict__ batch) {
    int warp = (blockIdx.x * blockDim.x + threadIdx.x) >> 5;
    if (warp >= NNODES) return;
    int lane = threadIdx.x & 31;
    int g = lane >> 2;
    int c4 = lane & 3;
    int d = warp;
    float4 xr = ((const float4*)(g_xr2 + (size_t)d * HID))[c4];
    float4 aw = __ldg(&((const float4*)att)[c4]);
    float4 acc = make_float4(0.f, 0.f, 0.f, 0.f);
    float den = 0.f;
    int deg = min(g_count[d], CAP);
    const int* slot = g_slot + (size_t)d * CAP;
    for (int blk = 0; blk < deg; blk += 32) {
        int nn = min(32, deg - blk);                  // warp-uniform
        int myidx = (lane < nn) ? slot[blk + lane] : 0;
        for (int j = 0; j < nn; j += 8) {             // warp-uniform trip count
            int na = nn - j;                          // active groups this iter
            int s = __shfl_sync(0xffffffffu, myidx, j + g);   // g>=na reads lane<nn? may read zeroed lane, safe
            float4 xv = ((const float4*)(g_xl2 + (size_t)s * HID))[c4];
            float p = lrelu(xv.x + xr.x) * aw.x + lrelu(xv.y + xr.y) * aw.y
                    + lrelu(xv.z + xr.z) * aw.z + lrelu(xv.w + xr.w) * aw.w;
            p += __shfl_xor_sync(0xffffffffu, p, 1);
            p += __shfl_xor_sync(0xffffffffu, p, 2);
            float e = (g < na) ? __expf(p) : 0.f;
            acc.x += e * xv.x; acc.y += e * xv.y; acc.z += e * xv.z; acc.w += e * xv.w;
            den += e;
        }
    }
    // cross-group reduction (groups differ, channel-quad aligned): xor 4, 8, 16
    #pragma unroll
    for (int off = 4; off <= 16; off <<= 1) {
        acc.x += __shfl_xor_sync(0xffffffffu, acc.x, off);
        acc.y += __shfl_xor_sync(0xffffffffu, acc.y, off);
        acc.z += __shfl_xor_sync(0xffffffffu, acc.z, off);
        acc.w += __shfl_xor_sync(0xffffffffu, acc.w, off);
        den   += __shfl_xor_sync(0xffffffffu, den,   off);
    }
    if (g == 0) {     // lanes 0..3 hold channel quads 0..3
        float inv = 1.f / (den + 1e-16f);
        float4 b = __ldg(&((const float4*)bias)[c4]);
        float4 o;
        o.x = elu1f(fmaf(acc.x, inv, b.x));
        o.y = elu1f(fmaf(acc.y, inv, b.y));
        o.z = elu1f(fmaf(acc.z, inv, b.z));
        o.w = elu1f(fmaf(acc.w, inv, b.w));
        int bb = batch[d];
        red_add_v4(g_pool + bb * HID + 4 * c4, o);
        if (c4 == 0) atomicAdd(&g_cnt[bb], 1.f);
    }
}

// ---------------- final MLP ----------------
__global__ void mlp_kernel(const float* __restrict__ w1, const float* __restrict__ b1,
                           const float* __restrict__ w2, const float* __restrict__ b2,
                           const float* __restrict__ w3, const float* __restrict__ b3,
                           float* __restrict__ out) {
    __shared__ float s1[HID * 32], sb1[32];
    __shared__ float s2[32 * HID], sb2[HID];
    __shared__ float s3[HID * 32], sb3[32];
    int tid = threadIdx.x;
    for (int i = tid; i < HID * 32; i += 256) s1[i] = w1[i];
    for (int i = tid; i < 32 * HID; i += 256) s2[i] = w2[i];
    for (int i = tid; i < HID * 32; i += 256) s3[i] = w3[i];
    if (tid < 32) { sb1[tid] = b1[tid]; sb3[tid] = b3[tid]; }
    if (tid < HID) sb2[tid] = b2[tid];
    __syncthreads();
    int b = tid;
    float cnt = fmaxf(g_cnt[b], 1.f);
    float h[HID];
    #pragma unroll
    for (int c = 0; c < HID; c++) h[c] = g_pool[b * HID + c] / cnt;
    float t1[32];
    #pragma unroll
    for (int j = 0; j < 32; j++) {
        float s = sb1[j];
        #pragma unroll
        for (int k = 0; k < HID; k++) s += h[k] * s1[k * 32 + j];
        t1[j] = elu1f(s);
    }
    float t2[HID];
    #pragma unroll
    for (int j = 0; j < HID; j++) {
        float s = sb2[j];
        #pragma unroll
        for (int k = 0; k < 32; k++) s += t1[k] * s2[k * HID + j];
        t2[j] = elu1f(s);
    }
    #pragma unroll
    for (int j = 0; j < 32; j++) {
        float s = sb3[j];
        #pragma unroll
        for (int k = 0; k < HID; k++) s += t2[k] * s3[k * 32 + j];
        out[b * 32 + j] = s;
    }
}

// ---------------- launch ----------------
extern "C" void kernel_launch(void* const* d_in, const int* in_sizes, int n_in,
                              void* d_out, int out_size) {
    const float* x     = (const float*)d_in[0];
    const int*   ei    = (const int*)  d_in[1];
    const int*   batch = (const int*)  d_in[2];
    const float* wl1   = (const float*)d_in[3];
    const float* bl1   = (const float*)d_in[4];
    const float* wr1   = (const float*)d_in[5];
    const float* br1   = (const float*)d_in[6];
    const float* att1  = (const float*)d_in[7];
    const float* bias1 = (const float*)d_in[8];
    const float* wl2   = (const float*)d_in[9];
    const float* bl2   = (const float*)d_in[10];
    const float* wr2   = (const float*)d_in[11];
    const float* br2   = (const float*)d_in[12];
    const float* att2  = (const float*)d_in[13];
    const float* bias2 = (const float*)d_in[14];
    const float* wm1   = (const float*)d_in[15];
    const float* bm1   = (const float*)d_in[16];
    const float* wm2   = (const float*)d_in[17];
    const float* bm2   = (const float*)d_in[18];
    const float* wm3   = (const float*)d_in[19];
    const float* bm3   = (const float*)d_in[20];
    const int* src = ei;
    const int* dst = ei + NEDGES;
    float* out = (float*)d_out;

    zero_kernel<<<(NNODES + 511) / 512, 512>>>();
    fusedA_kernel<<<GG + GH, 256>>>(x, wl1, bl1, wr1, br1, src, dst);
    edge1_fused_kernel<<<(NNODES * 32 + 255) / 256, 256>>>(att1, bias1);
    gemm2_kernel<<<(NNODES + 127) / 128, 256>>>(wl2, bl2, wr2, br2);
    edge2_fused_kernel<<<(NNODES * 32 + 255) / 256, 256>>>(att2, bias2, batch);
    mlp_kernel<<<1, 256>>>(wm1, bm1, wm2, bm2, wm3, bm3, out);
}